// round 14
// baseline (speedup 1.0000x reference)
#include <cuda_runtime.h>
#include <cuda_bf16.h>
#include <cuda_fp16.h>

#define N_NODES 40000
#define N_EDGES 480000
#define NPLANE  (N_NODES * 64)

#define TBL    4096
#define LMAXF  0.86603f
#define HSTEP  (LMAXF / (TBL - 1))
#define INVH   ((TBL - 1) / LMAXF)

__device__ __align__(16) float g_hs[N_NODES * 64];
__device__ __align__(16) float g_hv[3 * N_NODES * 64];
__device__ __align__(16) float g_sc[N_NODES * 320];
__device__ __align__(16) float g_agg[(size_t)N_NODES * 512];
__device__ __align__(16) __half g_tblh[TBL * 256];
__device__ int g_cnt[N_NODES];
__device__ __align__(16) float4 g_ev4[N_EDGES];   // sorted: {v0,v1,v2,sender}
__device__ int g_rr[N_EDGES];                     // sorted receiver ids

__device__ __forceinline__ float swishf(float x) {
    return x / (1.0f + __expf(-x));
}

typedef unsigned long long u64;
__device__ __forceinline__ u64 pack2(float lo, float hi) {
    u64 r; asm("mov.b64 %0, {%1, %2};" : "=l"(r) : "f"(lo), "f"(hi)); return r;
}
__device__ __forceinline__ float2 unpack2(u64 v) {
    float2 r; asm("mov.b64 {%0, %1}, %2;" : "=f"(r.x), "=f"(r.y) : "l"(v)); return r;
}
__device__ __forceinline__ void ffma2(u64& d, u64 a, u64 b) {
    asm("fma.rn.f32x2 %0, %1, %2, %0;" : "+l"(d) : "l"(a), "l"(b));
}
__device__ __forceinline__ float4 half4_to_float4(uint2 a) {
    float2 lo = __half22float2(*(const __half2*)&a.x);
    float2 hi = __half22float2(*(const __half2*)&a.y);
    return make_float4(lo.x, lo.y, hi.x, hi.y);
}

#define INV8F   0.3535533905932738f
#define INV64F  0.125f
#define INV128F 0.08838834764831845f
#define INVNN   0.28867513459481287f
#define SQRT3F  1.7320508075688772f
#define SQRT2F  1.4142135623730951f
#define PI_F    3.14159265358979323846f

// =====================================================================
// Edge sort (receiver order) — scatter writes reordered payload
// =====================================================================
__global__ void k_hist(const int* __restrict__ receivers) {
    int e = blockIdx.x * blockDim.x + threadIdx.x;
    if (e < N_EDGES) atomicAdd(&g_cnt[__ldg(receivers + e)], 1);
}

#define SCAN_T 1024
#define SCAN_C 40
__global__ void __launch_bounds__(SCAN_T) k_scan() {
    __shared__ int psum[SCAN_T];
    int tid = threadIdx.x;
    int base = tid * SCAN_C;
    int local[SCAN_C];
    int s = 0;
#pragma unroll
    for (int i = 0; i < SCAN_C; i++) {
        int idx = base + i;
        int v = (idx < N_NODES) ? g_cnt[idx] : 0;
        local[i] = v; s += v;
    }
    psum[tid] = s;
    __syncthreads();
    for (int d = 1; d < SCAN_T; d <<= 1) {
        int v = (tid >= d) ? psum[tid - d] : 0;
        __syncthreads();
        psum[tid] += v;
        __syncthreads();
    }
    int off = psum[tid] - s;
#pragma unroll
    for (int i = 0; i < SCAN_C; i++) {
        int idx = base + i;
        if (idx < N_NODES) { g_cnt[idx] = off; off += local[i]; }
    }
}

__global__ void k_scatter(const int* __restrict__ receivers,
                          const int* __restrict__ senders,
                          const float* __restrict__ vectors) {
    int e = blockIdx.x * blockDim.x + threadIdx.x;
    if (e < N_EDGES) {
        int r = __ldg(receivers + e);
        int pos = atomicAdd(&g_cnt[r], 1);
        float v0 = __ldg(vectors + 3 * e + 0);
        float v1 = __ldg(vectors + 3 * e + 1);
        float v2 = __ldg(vectors + 3 * e + 2);
        int s = __ldg(senders + e);
        g_ev4[pos] = make_float4(v0, v1, v2, __int_as_float(s));
        g_rr[pos] = r;
    }
}

// =====================================================================
// Table builder: mix(len) for TBL grid points -> fp16 rows
// =====================================================================
__global__ void __launch_bounds__(256) k_table(
    const float* __restrict__ W1, const float* __restrict__ W2,
    const float* __restrict__ W3)
{
    extern __shared__ float smw[];
    float* sW2 = smw;            // 64*64
    float* sW3 = smw + 4096;     // 64*256
    __shared__ float rb_s[4][8], h1_s[4][64], h2_s[4][64];
    int tid = threadIdx.x;
    for (int i = tid; i < 4096; i += 256)  sW2[i] = __ldg(W2 + i);
    for (int i = tid; i < 16384; i += 256) sW3[i] = __ldg(W3 + i);
    __syncthreads();

    int g = tid >> 6, t = tid & 63;
#pragma unroll 1
    for (int rep = 0; rep < 4; rep++) {
        int row = blockIdx.x * 16 + rep * 4 + g;
        float x = row * HSTEP;
        if (t < 8) {
            float k = (float)(t + 1);
            float s = (x > 0.f) ? (sinf(k * PI_F * x) / x) : (k * PI_F);
            float x2 = x * x, x3 = x2 * x, x6 = x3 * x3, x7 = x6 * x, x8 = x7 * x;
            float env = (x < 1.f) ? (1.f - 28.f * x6 + 48.f * x7 - 21.f * x8) : 0.f;
            rb_s[g][t] = SQRT2F * s * env;
        }
        __syncthreads();
        float a = 0.f;
#pragma unroll
        for (int k = 0; k < 8; k++) a += rb_s[g][k] * __ldg(W1 + k * 64 + t);
        h1_s[g][t] = swishf(a * INV8F);
        __syncthreads();
        float b = 0.f;
#pragma unroll 8
        for (int i = 0; i < 64; i++) b += h1_s[g][i] * sW2[i * 64 + t];
        h2_s[g][t] = swishf(b * INV64F);
        __syncthreads();
#pragma unroll
        for (int jj = 0; jj < 4; jj++) {
            float c = 0.f;
#pragma unroll 8
            for (int i = 0; i < 64; i++) c += h2_s[g][i] * sW3[i * 256 + t + 64 * jj];
            g_tblh[row * 256 + t + 64 * jj] = __float2half(c * INV64F);
        }
        __syncthreads();
    }
}

// =====================================================================
// Kernel 1: node "up" + species skip. Warp per 2 nodes.
// x-values staged PRE-DUPLICATED (u64 pairs) in smem: the FFMA2
// broadcast operand comes straight from LDS.64, no pack2 in the loop.
// =====================================================================
__global__ void __launch_bounds__(256) k_node_up(
    const float* __restrict__ ns, const float* __restrict__ nv,
    const int* __restrict__ specie,
    const float* __restrict__ Wus, const float* __restrict__ Wuv,
    const float* __restrict__ Wss, const float* __restrict__ Wsv)
{
    __shared__ __align__(16) u64 xs[8][2][64];     // (x,x) pairs
    __shared__ __align__(16) u64 xv[8][2][192];    // (v,v) pairs
    int w = threadIdx.x >> 5, t = threadIdx.x & 31;
    int n0 = (blockIdx.x * 8 + w) * 2;

#pragma unroll
    for (int nl = 0; nl < 2; nl++) {
        int n = n0 + nl;
        float a = __ldg(ns + n * 64 + t);
        float b = __ldg(ns + n * 64 + t + 32);
        xs[w][nl][t]      = pack2(a, a);
        xs[w][nl][t + 32] = pack2(b, b);
#pragma unroll
        for (int q = 0; q < 6; q++) {
            float v = __ldg(nv + n * 192 + t + 32 * q);
            xv[w][nl][t + 32 * q] = pack2(v, v);
        }
    }
    __syncwarp();

    int sp0 = __ldg(specie + n0);
    int sp1 = __ldg(specie + n0 + 1);
    const float* Ws0 = Wss + sp0 * 8192;
    const float* Ws1 = Wss + sp1 * 8192;
    const float* Wv0 = Wsv + sp0 * 4096;
    const float* Wv1 = Wsv + sp1 * 4096;

    u64 aU[2] = {}, aV0[2] = {}, aV1[2] = {}, aV2[2] = {};
    u64 aS0[2] = {}, aS1[2] = {};
    u64 aC0[2] = {}, aC1[2] = {}, aC2[2] = {};

#pragma unroll 4
    for (int i = 0; i < 64; i++) {
        u64 wu = *(const u64*)(Wus + i * 64 + 2 * t);
        u64 wv = *(const u64*)(Wuv + i * 64 + 2 * t);
        ulonglong2 wsA = *(const ulonglong2*)(Ws0 + i * 128 + 4 * t);
        ulonglong2 wsB = *(const ulonglong2*)(Ws1 + i * 128 + 4 * t);
        u64 wcA = *(const u64*)(Wv0 + i * 64 + 2 * t);
        u64 wcB = *(const u64*)(Wv1 + i * 64 + 2 * t);

        {
            u64 xx = xs[w][0][i];
            u64 p0 = xv[w][0][3 * i], p1 = xv[w][0][3 * i + 1], p2 = xv[w][0][3 * i + 2];
            ffma2(aU[0], xx, wu);
            ffma2(aV0[0], p0, wv); ffma2(aV1[0], p1, wv); ffma2(aV2[0], p2, wv);
            ffma2(aS0[0], xx, wsA.x); ffma2(aS1[0], xx, wsA.y);
            ffma2(aC0[0], p0, wcA); ffma2(aC1[0], p1, wcA); ffma2(aC2[0], p2, wcA);
        }
        {
            u64 xx = xs[w][1][i];
            u64 p0 = xv[w][1][3 * i], p1 = xv[w][1][3 * i + 1], p2 = xv[w][1][3 * i + 2];
            ffma2(aU[1], xx, wu);
            ffma2(aV0[1], p0, wv); ffma2(aV1[1], p1, wv); ffma2(aV2[1], p2, wv);
            ffma2(aS0[1], xx, wsB.x); ffma2(aS1[1], xx, wsB.y);
            ffma2(aC0[1], p0, wcB); ffma2(aC1[1], p1, wcB); ffma2(aC2[1], p2, wcB);
        }
    }

#pragma unroll
    for (int nl = 0; nl < 2; nl++) {
        int n = n0 + nl;
        float2 u = unpack2(aU[nl]);
        *(float2*)(g_hs + n * 64 + 2 * t) = make_float2(u.x * INV64F, u.y * INV64F);
        float2 b0 = unpack2(aV0[nl]), b1 = unpack2(aV1[nl]), b2 = unpack2(aV2[nl]);
        *(float2*)(g_hv + 0 * NPLANE + n * 64 + 2 * t) = make_float2(b0.x * INV64F, b0.y * INV64F);
        *(float2*)(g_hv + 1 * NPLANE + n * 64 + 2 * t) = make_float2(b1.x * INV64F, b1.y * INV64F);
        *(float2*)(g_hv + 2 * NPLANE + n * 64 + 2 * t) = make_float2(b2.x * INV64F, b2.y * INV64F);

        float* sc = g_sc + (size_t)n * 320;
        float2 s0 = unpack2(aS0[nl]), s1 = unpack2(aS1[nl]);
        *(float4*)(sc + 4 * t) =
            make_float4(s0.x * INV64F, s0.y * INV64F, s1.x * INV64F, s1.y * INV64F);
        float2 c0 = unpack2(aC0[nl]), c1 = unpack2(aC1[nl]), c2 = unpack2(aC2[nl]);
        float* scv = sc + 128 + 6 * t;
        scv[0] = c0.x * INV64F; scv[1] = c1.x * INV64F; scv[2] = c2.x * INV64F;
        scv[3] = c0.y * INV64F; scv[4] = c1.y * INV64F; scv[5] = c2.y * INV64F;
    }
}

// =====================================================================
// Kernel 2: edge kernel, receiver-sorted + run-merged atomics.
// Edge payload pre-gathered by k_scatter; per-iteration values come
// from register broadcasts (shfl), not dependent LDG chains.
// =====================================================================
#define EPW 16
#define K2W 8
__global__ void __launch_bounds__(256) k_edge()
{
    int w = threadIdx.x >> 5, t = threadIdx.x & 31;
    int e0 = (blockIdx.x * K2W + w) * EPW;

    float4 ed = make_float4(0.f, 0.f, 0.f, 0.f);
    int rrl = 0;
    if (t < EPW) {
        ed = g_ev4[e0 + t];
        rrl = __ldg(g_rr + e0 + t);
    }

    float4 aS  = make_float4(0,0,0,0), aV0 = make_float4(0,0,0,0);
    float4 aV1 = make_float4(0,0,0,0), aV2 = make_float4(0,0,0,0);
    int curr = -1;
    int j = 4 * (t & 15);

#pragma unroll 1
    for (int el = 0; el < EPW; el++) {
        float v0 = __shfl_sync(0xffffffffu, ed.x, el);
        float v1 = __shfl_sync(0xffffffffu, ed.y, el);
        float v2 = __shfl_sync(0xffffffffu, ed.z, el);
        int s = __shfl_sync(0xffffffffu, __float_as_int(ed.w), el);
        int r = __shfl_sync(0xffffffffu, rrl, el);

        float len = sqrtf(v0 * v0 + v1 * v1 + v2 * v2);
        float inv = 1.f / ((len == 0.f) ? 1.f : len);
        float u0 = v0 * inv, u1 = v1 * inv, u2 = v2 * inv;
        float y0 = SQRT3F * u0, y1 = SQRT3F * u1, y2 = SQRT3F * u2;

        float uu = len * INVH;
        int i0 = (int)uu;
        if (i0 > TBL - 2) i0 = TBL - 2;
        float f = uu - (float)i0;
        const __half* r0 = g_tblh + i0 * 256;

        float4 a0 = half4_to_float4(*(const uint2*)(r0 + 4 * t));
        float4 a1 = half4_to_float4(*(const uint2*)(r0 + 256 + 4 * t));
        float4 b0 = half4_to_float4(*(const uint2*)(r0 + 128 + 4 * t));
        float4 b1 = half4_to_float4(*(const uint2*)(r0 + 384 + 4 * t));

        float4 m1 = make_float4(a0.x + f * (a1.x - a0.x), a0.y + f * (a1.y - a0.y),
                                a0.z + f * (a1.z - a0.z), a0.w + f * (a1.w - a0.w));
        float4 m2 = make_float4(b0.x + f * (b1.x - b0.x), b0.y + f * (b1.y - b0.y),
                                b0.z + f * (b1.z - b0.z), b0.w + f * (b1.w - b0.w));

        const float4 ms  = *(const float4*)(g_hs +              s * 64 + j);
        const float4 mv0 = *(const float4*)(g_hv + 0 * NPLANE + s * 64 + j);
        const float4 mv1 = *(const float4*)(g_hv + 1 * NPLANE + s * 64 + j);
        const float4 mv2 = *(const float4*)(g_hv + 2 * NPLANE + s * 64 + j);

        float4 os, ov0, ov1, ov2;
        if (t < 16) {
            os  = make_float4(ms.x * m1.x, ms.y * m1.y, ms.z * m1.z, ms.w * m1.w);
            ov0 = make_float4(mv0.x * m2.x, mv0.y * m2.y, mv0.z * m2.z, mv0.w * m2.w);
            ov1 = make_float4(mv1.x * m2.x, mv1.y * m2.y, mv1.z * m2.z, mv1.w * m2.w);
            ov2 = make_float4(mv2.x * m2.x, mv2.y * m2.y, mv2.z * m2.z, mv2.w * m2.w);
        } else {
            float tpx = mv0.x * u0 + mv1.x * u1 + mv2.x * u2;
            float tpy = mv0.y * u0 + mv1.y * u1 + mv2.y * u2;
            float tpz = mv0.z * u0 + mv1.z * u1 + mv2.z * u2;
            float tpw = mv0.w * u0 + mv1.w * u1 + mv2.w * u2;
            os  = make_float4(tpx * m1.x, tpy * m1.y, tpz * m1.z, tpw * m1.w);
            ov0 = make_float4(ms.x * y0 * m2.x, ms.y * y0 * m2.y, ms.z * y0 * m2.z, ms.w * y0 * m2.w);
            ov1 = make_float4(ms.x * y1 * m2.x, ms.y * y1 * m2.y, ms.z * y1 * m2.z, ms.w * y1 * m2.w);
            ov2 = make_float4(ms.x * y2 * m2.x, ms.y * y2 * m2.y, ms.z * y2 * m2.z, ms.w * y2 * m2.w);
        }

        if (r != curr) {
            if (curr >= 0) {
                float* base = g_agg + (size_t)curr * 512;
                atomicAdd((float4*)(base + 4 * t),       aS);
                atomicAdd((float4*)(base + 128 + 4 * t), aV0);
                atomicAdd((float4*)(base + 256 + 4 * t), aV1);
                atomicAdd((float4*)(base + 384 + 4 * t), aV2);
            }
            curr = r;
            aS = os; aV0 = ov0; aV1 = ov1; aV2 = ov2;
        } else {
            aS.x += os.x;  aS.y += os.y;  aS.z += os.z;  aS.w += os.w;
            aV0.x += ov0.x; aV0.y += ov0.y; aV0.z += ov0.z; aV0.w += ov0.w;
            aV1.x += ov1.x; aV1.y += ov1.y; aV1.z += ov1.z; aV1.w += ov1.w;
            aV2.x += ov2.x; aV2.y += ov2.y; aV2.z += ov2.z; aV2.w += ov2.w;
        }
    }
    if (curr >= 0) {
        float* base = g_agg + (size_t)curr * 512;
        atomicAdd((float4*)(base + 4 * t),       aS);
        atomicAdd((float4*)(base + 128 + 4 * t), aV0);
        atomicAdd((float4*)(base + 256 + 4 * t), aV1);
        atomicAdd((float4*)(base + 384 + 4 * t), aV2);
    }
}

// =====================================================================
// Kernel 3: node "down" + skip + gate. 4 nodes/warp, vec weights.
// =====================================================================
__global__ void __launch_bounds__(128) k_node_down(
    const float* __restrict__ Wds, const float* __restrict__ Wdv,
    float* __restrict__ out)
{
    __shared__ __align__(16) float agi[4][512][4];
    int w = threadIdx.x >> 5, t = threadIdx.x & 31;
    int n0 = (blockIdx.x * 4 + w) * 4;

#pragma unroll
    for (int nl = 0; nl < 4; nl++) {
        const float4* src = (const float4*)(g_agg + (size_t)(n0 + nl) * 512);
#pragma unroll
        for (int q = 0; q < 4; q++) {
            float4 v = src[t + 32 * q];
            int i = 4 * t + 128 * q;
            agi[w][i + 0][nl] = v.x;
            agi[w][i + 1][nl] = v.y;
            agi[w][i + 2][nl] = v.z;
            agi[w][i + 3][nl] = v.w;
        }
    }
    __syncwarp();

    const float SCALE = INV128F * INVNN;

    u64 accS[4][2] = {};
#pragma unroll 4
    for (int i = 0; i < 128; i++) {
        float4 w4 = *(const float4*)(Wds + i * 128 + 4 * t);
        const u64* xp = (const u64*)agi[w][i];
        u64 x0 = xp[0], x1 = xp[1];
        u64 wp;
        wp = pack2(w4.x, w4.x); ffma2(accS[0][0], wp, x0); ffma2(accS[0][1], wp, x1);
        wp = pack2(w4.y, w4.y); ffma2(accS[1][0], wp, x0); ffma2(accS[1][1], wp, x1);
        wp = pack2(w4.z, w4.z); ffma2(accS[2][0], wp, x0); ffma2(accS[2][1], wp, x1);
        wp = pack2(w4.w, w4.w); ffma2(accS[3][0], wp, x0); ffma2(accS[3][1], wp, x1);
    }

    u64 accV[2][3][2] = {};
#pragma unroll 4
    for (int i = 0; i < 128; i++) {
        float2 w2 = *(const float2*)(Wdv + i * 64 + 2 * t);
        u64 wp0 = pack2(w2.x, w2.x), wp1 = pack2(w2.y, w2.y);
#pragma unroll
        for (int c = 0; c < 3; c++) {
            const u64* xp = (const u64*)agi[w][128 + 128 * c + i];
            u64 x0 = xp[0], x1 = xp[1];
            ffma2(accV[0][c][0], wp0, x0); ffma2(accV[0][c][1], wp0, x1);
            ffma2(accV[1][c][0], wp1, x0); ffma2(accV[1][c][1], wp1, x1);
        }
    }

#pragma unroll
    for (int nl = 0; nl < 4; nl++) {
        int n = n0 + nl;
        int p = nl >> 1, hi = nl & 1;
        const float* sc = g_sc + (size_t)n * 320;
        float4 sc4 = *(const float4*)(sc + 4 * t);
        float ds0, ds1, ds2, ds3;
        {
            float2 v0 = unpack2(accS[0][p]); ds0 = (hi ? v0.y : v0.x) * SCALE + sc4.x;
            float2 v1 = unpack2(accS[1][p]); ds1 = (hi ? v1.y : v1.x) * SCALE + sc4.y;
            float2 v2 = unpack2(accS[2][p]); ds2 = (hi ? v2.y : v2.x) * SCALE + sc4.z;
            float2 v3 = unpack2(accS[3][p]); ds3 = (hi ? v3.y : v3.x) * SCALE + sc4.w;
        }
        float sg0 = swishf(ds0), sg1 = swishf(ds1);
        float sg2 = swishf(ds2), sg3 = swishf(ds3);

        float* o = out + (size_t)n * 256;
        if (t < 16)
            *(float4*)(o + 4 * t) = make_float4(sg0, sg1, sg2, sg3);

        int src = 16 + (t >> 1);
        float gA = __shfl_sync(0xffffffffu, sg0, src);
        float gB = __shfl_sync(0xffffffffu, sg1, src);
        float gC = __shfl_sync(0xffffffffu, sg2, src);
        float gD = __shfl_sync(0xffffffffu, sg3, src);
        float g0 = (t & 1) ? gC : gA;
        float g1 = (t & 1) ? gD : gB;

        const float* scv = sc + 128 + 6 * t;
        float ev[6];
#pragma unroll
        for (int c = 0; c < 3; c++) {
            float2 v0 = unpack2(accV[0][c][p]);
            float2 v1 = unpack2(accV[1][c][p]);
            ev[c]     = ((hi ? v0.y : v0.x) * SCALE + scv[c])     * g0;
            ev[3 + c] = ((hi ? v1.y : v1.x) * SCALE + scv[3 + c]) * g1;
        }
        float* ov = o + 64 + 6 * t;
        *(float2*)(ov + 0) = make_float2(ev[0], ev[1]);
        *(float2*)(ov + 2) = make_float2(ev[2], ev[3]);
        *(float2*)(ov + 4) = make_float2(ev[4], ev[5]);
    }
}

// =====================================================================
extern "C" void kernel_launch(void* const* d_in, const int* in_sizes, int n_in,
                              void* d_out, int out_size)
{
    const float* vectors      = (const float*)d_in[0];
    const float* node_scalars = (const float*)d_in[1];
    const float* node_vectors = (const float*)d_in[2];
    const int*   node_specie  = (const int*)  d_in[3];
    const int*   senders      = (const int*)  d_in[4];
    const int*   receivers    = (const int*)  d_in[5];
    const float* W_up_s       = (const float*)d_in[6];
    const float* W_up_v       = (const float*)d_in[7];
    const float* W_skip_s     = (const float*)d_in[8];
    const float* W_skip_v     = (const float*)d_in[9];
    const float* W_mlp1       = (const float*)d_in[10];
    const float* W_mlp2       = (const float*)d_in[11];
    const float* W_mlp3       = (const float*)d_in[12];
    const float* W_down_s     = (const float*)d_in[13];
    const float* W_down_v     = (const float*)d_in[14];
    float* out = (float*)d_out;

    void* aggp = nullptr; cudaGetSymbolAddress(&aggp, g_agg);
    void* cntp = nullptr; cudaGetSymbolAddress(&cntp, g_cnt);
    cudaMemsetAsync(aggp, 0, (size_t)N_NODES * 512 * sizeof(float));
    cudaMemsetAsync(cntp, 0, N_NODES * sizeof(int));

    // receiver-sorted permutation with payload materialization
    k_hist<<<(N_EDGES + 255) / 256, 256>>>(receivers);
    k_scan<<<1, SCAN_T>>>();
    k_scatter<<<(N_EDGES + 255) / 256, 256>>>(receivers, senders, vectors);

    // node_up
    k_node_up<<<N_NODES / 16, 256>>>(node_scalars, node_vectors, node_specie,
                                     W_up_s, W_up_v, W_skip_s, W_skip_v);

    // radial-MLP lookup table (fp16)
    cudaFuncSetAttribute(k_table, cudaFuncAttributeMaxDynamicSharedMemorySize, 20480 * 4);
    k_table<<<TBL / 16, 256, 20480 * 4>>>(W_mlp1, W_mlp2, W_mlp3);

    k_edge<<<N_EDGES / (K2W * EPW), 256>>>();

    k_node_down<<<N_NODES / 16, 128>>>(W_down_s, W_down_v, out);
}

// round 15
// speedup vs baseline: 1.0905x; 1.0905x over previous
#include <cuda_runtime.h>
#include <cuda_bf16.h>
#include <cuda_fp16.h>

#define N_NODES 40000
#define N_EDGES 480000
#define NPLANE  (N_NODES * 64)

#define TBL    4096
#define LMAXF  0.86603f
#define HSTEP  (LMAXF / (TBL - 1))
#define INVH   ((TBL - 1) / LMAXF)

__device__ __align__(16) float g_hs[N_NODES * 64];
__device__ __align__(16) float g_hv[3 * N_NODES * 64];
__device__ __align__(16) float g_sc[N_NODES * 320];
__device__ __align__(16) float g_agg[(size_t)N_NODES * 512];
__device__ __align__(16) __half g_tblh[TBL * 256];
__device__ int g_cnt[N_NODES];
__device__ __align__(16) float4 g_ev4[N_EDGES];   // sorted: {v0,v1,v2,sender}
__device__ int g_rr[N_EDGES];                     // sorted receiver ids

__device__ __forceinline__ float swishf(float x) {
    return x / (1.0f + __expf(-x));
}

typedef unsigned long long u64;
__device__ __forceinline__ u64 pack2(float lo, float hi) {
    u64 r; asm("mov.b64 %0, {%1, %2};" : "=l"(r) : "f"(lo), "f"(hi)); return r;
}
__device__ __forceinline__ float2 unpack2(u64 v) {
    float2 r; asm("mov.b64 {%0, %1}, %2;" : "=f"(r.x), "=f"(r.y) : "l"(v)); return r;
}
__device__ __forceinline__ void ffma2(u64& d, u64 a, u64 b) {
    asm("fma.rn.f32x2 %0, %1, %2, %0;" : "+l"(d) : "l"(a), "l"(b));
}
__device__ __forceinline__ float4 half4_to_float4(uint2 a) {
    float2 lo = __half22float2(*(const __half2*)&a.x);
    float2 hi = __half22float2(*(const __half2*)&a.y);
    return make_float4(lo.x, lo.y, hi.x, hi.y);
}

#define INV8F   0.3535533905932738f
#define INV64F  0.125f
#define INV128F 0.08838834764831845f
#define INVNN   0.28867513459481287f
#define SQRT3F  1.7320508075688772f
#define SQRT2F  1.4142135623730951f
#define PI_F    3.14159265358979323846f

// =====================================================================
// Edge sort (receiver order) — scatter writes reordered payload
// =====================================================================
__global__ void k_hist(const int* __restrict__ receivers) {
    int e = blockIdx.x * blockDim.x + threadIdx.x;
    if (e < N_EDGES) atomicAdd(&g_cnt[__ldg(receivers + e)], 1);
}

#define SCAN_T 1024
#define SCAN_C 40
__global__ void __launch_bounds__(SCAN_T) k_scan() {
    __shared__ int psum[SCAN_T];
    int tid = threadIdx.x;
    int base = tid * SCAN_C;
    int local[SCAN_C];
    int s = 0;
#pragma unroll
    for (int i = 0; i < SCAN_C; i++) {
        int idx = base + i;
        int v = (idx < N_NODES) ? g_cnt[idx] : 0;
        local[i] = v; s += v;
    }
    psum[tid] = s;
    __syncthreads();
    for (int d = 1; d < SCAN_T; d <<= 1) {
        int v = (tid >= d) ? psum[tid - d] : 0;
        __syncthreads();
        psum[tid] += v;
        __syncthreads();
    }
    int off = psum[tid] - s;
#pragma unroll
    for (int i = 0; i < SCAN_C; i++) {
        int idx = base + i;
        if (idx < N_NODES) { g_cnt[idx] = off; off += local[i]; }
    }
}

__global__ void k_scatter(const int* __restrict__ receivers,
                          const int* __restrict__ senders,
                          const float* __restrict__ vectors) {
    int e = blockIdx.x * blockDim.x + threadIdx.x;
    if (e < N_EDGES) {
        int r = __ldg(receivers + e);
        int pos = atomicAdd(&g_cnt[r], 1);
        float v0 = __ldg(vectors + 3 * e + 0);
        float v1 = __ldg(vectors + 3 * e + 1);
        float v2 = __ldg(vectors + 3 * e + 2);
        int s = __ldg(senders + e);
        g_ev4[pos] = make_float4(v0, v1, v2, __int_as_float(s));
        g_rr[pos] = r;
    }
}

// =====================================================================
// Table builder: mix(len) for TBL grid points -> fp16 rows
// =====================================================================
__global__ void __launch_bounds__(256) k_table(
    const float* __restrict__ W1, const float* __restrict__ W2,
    const float* __restrict__ W3)
{
    extern __shared__ float smw[];
    float* sW2 = smw;            // 64*64
    float* sW3 = smw + 4096;     // 64*256
    __shared__ float rb_s[4][8], h1_s[4][64], h2_s[4][64];
    int tid = threadIdx.x;
    for (int i = tid; i < 4096; i += 256)  sW2[i] = __ldg(W2 + i);
    for (int i = tid; i < 16384; i += 256) sW3[i] = __ldg(W3 + i);
    __syncthreads();

    int g = tid >> 6, t = tid & 63;
#pragma unroll 1
    for (int rep = 0; rep < 4; rep++) {
        int row = blockIdx.x * 16 + rep * 4 + g;
        float x = row * HSTEP;
        if (t < 8) {
            float k = (float)(t + 1);
            float s = (x > 0.f) ? (sinf(k * PI_F * x) / x) : (k * PI_F);
            float x2 = x * x, x3 = x2 * x, x6 = x3 * x3, x7 = x6 * x, x8 = x7 * x;
            float env = (x < 1.f) ? (1.f - 28.f * x6 + 48.f * x7 - 21.f * x8) : 0.f;
            rb_s[g][t] = SQRT2F * s * env;
        }
        __syncthreads();
        float a = 0.f;
#pragma unroll
        for (int k = 0; k < 8; k++) a += rb_s[g][k] * __ldg(W1 + k * 64 + t);
        h1_s[g][t] = swishf(a * INV8F);
        __syncthreads();
        float b = 0.f;
#pragma unroll 8
        for (int i = 0; i < 64; i++) b += h1_s[g][i] * sW2[i * 64 + t];
        h2_s[g][t] = swishf(b * INV64F);
        __syncthreads();
#pragma unroll
        for (int jj = 0; jj < 4; jj++) {
            float c = 0.f;
#pragma unroll 8
            for (int i = 0; i < 64; i++) c += h2_s[g][i] * sW3[i * 256 + t + 64 * jj];
            g_tblh[row * 256 + t + 64 * jj] = __float2half(c * INV64F);
        }
        __syncthreads();
    }
}

// =====================================================================
// Kernel 1 (R13): node "up" + species skip. Warp per 2 nodes.
// =====================================================================
__global__ void __launch_bounds__(256) k_node_up(
    const float* __restrict__ ns, const float* __restrict__ nv,
    const int* __restrict__ specie,
    const float* __restrict__ Wus, const float* __restrict__ Wuv,
    const float* __restrict__ Wss, const float* __restrict__ Wsv)
{
    __shared__ __align__(16) float xs[8][2][64];
    __shared__ __align__(16) float xv[8][2][192];
    int w = threadIdx.x >> 5, t = threadIdx.x & 31;
    int n0 = (blockIdx.x * 8 + w) * 2;

#pragma unroll
    for (int nl = 0; nl < 2; nl++) {
        int n = n0 + nl;
        xs[w][nl][t]      = __ldg(ns + n * 64 + t);
        xs[w][nl][t + 32] = __ldg(ns + n * 64 + t + 32);
#pragma unroll
        for (int q = 0; q < 6; q++)
            xv[w][nl][t + 32 * q] = __ldg(nv + n * 192 + t + 32 * q);
    }
    __syncwarp();

    int sp0 = __ldg(specie + n0);
    int sp1 = __ldg(specie + n0 + 1);
    const float* Ws0 = Wss + sp0 * 8192;
    const float* Ws1 = Wss + sp1 * 8192;
    const float* Wv0 = Wsv + sp0 * 4096;
    const float* Wv1 = Wsv + sp1 * 4096;

    u64 aU[2] = {}, aV0[2] = {}, aV1[2] = {}, aV2[2] = {};
    u64 aS0[2] = {}, aS1[2] = {};
    u64 aC0[2] = {}, aC1[2] = {}, aC2[2] = {};

#pragma unroll 4
    for (int i = 0; i < 64; i++) {
        u64 wu = *(const u64*)(Wus + i * 64 + 2 * t);
        u64 wv = *(const u64*)(Wuv + i * 64 + 2 * t);
        ulonglong2 wsA = *(const ulonglong2*)(Ws0 + i * 128 + 4 * t);
        ulonglong2 wsB = *(const ulonglong2*)(Ws1 + i * 128 + 4 * t);
        u64 wcA = *(const u64*)(Wv0 + i * 64 + 2 * t);
        u64 wcB = *(const u64*)(Wv1 + i * 64 + 2 * t);

        {
            float x = xs[w][0][i];
            float v0 = xv[w][0][3 * i], v1 = xv[w][0][3 * i + 1], v2 = xv[w][0][3 * i + 2];
            u64 xx = pack2(x, x);
            u64 p0 = pack2(v0, v0), p1 = pack2(v1, v1), p2 = pack2(v2, v2);
            ffma2(aU[0], xx, wu);
            ffma2(aV0[0], p0, wv); ffma2(aV1[0], p1, wv); ffma2(aV2[0], p2, wv);
            ffma2(aS0[0], xx, wsA.x); ffma2(aS1[0], xx, wsA.y);
            ffma2(aC0[0], p0, wcA); ffma2(aC1[0], p1, wcA); ffma2(aC2[0], p2, wcA);
        }
        {
            float x = xs[w][1][i];
            float v0 = xv[w][1][3 * i], v1 = xv[w][1][3 * i + 1], v2 = xv[w][1][3 * i + 2];
            u64 xx = pack2(x, x);
            u64 p0 = pack2(v0, v0), p1 = pack2(v1, v1), p2 = pack2(v2, v2);
            ffma2(aU[1], xx, wu);
            ffma2(aV0[1], p0, wv); ffma2(aV1[1], p1, wv); ffma2(aV2[1], p2, wv);
            ffma2(aS0[1], xx, wsB.x); ffma2(aS1[1], xx, wsB.y);
            ffma2(aC0[1], p0, wcB); ffma2(aC1[1], p1, wcB); ffma2(aC2[1], p2, wcB);
        }
    }

#pragma unroll
    for (int nl = 0; nl < 2; nl++) {
        int n = n0 + nl;
        float2 u = unpack2(aU[nl]);
        *(float2*)(g_hs + n * 64 + 2 * t) = make_float2(u.x * INV64F, u.y * INV64F);
        float2 b0 = unpack2(aV0[nl]), b1 = unpack2(aV1[nl]), b2 = unpack2(aV2[nl]);
        *(float2*)(g_hv + 0 * NPLANE + n * 64 + 2 * t) = make_float2(b0.x * INV64F, b0.y * INV64F);
        *(float2*)(g_hv + 1 * NPLANE + n * 64 + 2 * t) = make_float2(b1.x * INV64F, b1.y * INV64F);
        *(float2*)(g_hv + 2 * NPLANE + n * 64 + 2 * t) = make_float2(b2.x * INV64F, b2.y * INV64F);

        float* sc = g_sc + (size_t)n * 320;
        float2 s0 = unpack2(aS0[nl]), s1 = unpack2(aS1[nl]);
        *(float4*)(sc + 4 * t) =
            make_float4(s0.x * INV64F, s0.y * INV64F, s1.x * INV64F, s1.y * INV64F);
        float2 c0 = unpack2(aC0[nl]), c1 = unpack2(aC1[nl]), c2 = unpack2(aC2[nl]);
        float* scv = sc + 128 + 6 * t;
        scv[0] = c0.x * INV64F; scv[1] = c1.x * INV64F; scv[2] = c2.x * INV64F;
        scv[3] = c0.y * INV64F; scv[4] = c1.y * INV64F; scv[5] = c2.y * INV64F;
    }
}

// =====================================================================
// Kernel 2 (R13): edge kernel, receiver-sorted + run-merged atomics.
// =====================================================================
#define EPW 16
#define K2W 8
__global__ void __launch_bounds__(256) k_edge()
{
    int w = threadIdx.x >> 5, t = threadIdx.x & 31;
    int e0 = (blockIdx.x * K2W + w) * EPW;

    float4 ed = make_float4(0.f, 0.f, 0.f, 0.f);
    int rrl = 0;
    if (t < EPW) {
        ed = g_ev4[e0 + t];
        rrl = __ldg(g_rr + e0 + t);
    }

    float4 aS  = make_float4(0,0,0,0), aV0 = make_float4(0,0,0,0);
    float4 aV1 = make_float4(0,0,0,0), aV2 = make_float4(0,0,0,0);
    int curr = -1;
    int j = 4 * (t & 15);

#pragma unroll 1
    for (int el = 0; el < EPW; el++) {
        float v0 = __shfl_sync(0xffffffffu, ed.x, el);
        float v1 = __shfl_sync(0xffffffffu, ed.y, el);
        float v2 = __shfl_sync(0xffffffffu, ed.z, el);
        int s = __shfl_sync(0xffffffffu, __float_as_int(ed.w), el);
        int r = __shfl_sync(0xffffffffu, rrl, el);

        float len = sqrtf(v0 * v0 + v1 * v1 + v2 * v2);
        float inv = 1.f / ((len == 0.f) ? 1.f : len);
        float u0 = v0 * inv, u1 = v1 * inv, u2 = v2 * inv;
        float y0 = SQRT3F * u0, y1 = SQRT3F * u1, y2 = SQRT3F * u2;

        float uu = len * INVH;
        int i0 = (int)uu;
        if (i0 > TBL - 2) i0 = TBL - 2;
        float f = uu - (float)i0;
        const __half* r0 = g_tblh + i0 * 256;

        float4 a0 = half4_to_float4(*(const uint2*)(r0 + 4 * t));
        float4 a1 = half4_to_float4(*(const uint2*)(r0 + 256 + 4 * t));
        float4 b0 = half4_to_float4(*(const uint2*)(r0 + 128 + 4 * t));
        float4 b1 = half4_to_float4(*(const uint2*)(r0 + 384 + 4 * t));

        float4 m1 = make_float4(a0.x + f * (a1.x - a0.x), a0.y + f * (a1.y - a0.y),
                                a0.z + f * (a1.z - a0.z), a0.w + f * (a1.w - a0.w));
        float4 m2 = make_float4(b0.x + f * (b1.x - b0.x), b0.y + f * (b1.y - b0.y),
                                b0.z + f * (b1.z - b0.z), b0.w + f * (b1.w - b0.w));

        const float4 ms  = *(const float4*)(g_hs +              s * 64 + j);
        const float4 mv0 = *(const float4*)(g_hv + 0 * NPLANE + s * 64 + j);
        const float4 mv1 = *(const float4*)(g_hv + 1 * NPLANE + s * 64 + j);
        const float4 mv2 = *(const float4*)(g_hv + 2 * NPLANE + s * 64 + j);

        float4 os, ov0, ov1, ov2;
        if (t < 16) {
            os  = make_float4(ms.x * m1.x, ms.y * m1.y, ms.z * m1.z, ms.w * m1.w);
            ov0 = make_float4(mv0.x * m2.x, mv0.y * m2.y, mv0.z * m2.z, mv0.w * m2.w);
            ov1 = make_float4(mv1.x * m2.x, mv1.y * m2.y, mv1.z * m2.z, mv1.w * m2.w);
            ov2 = make_float4(mv2.x * m2.x, mv2.y * m2.y, mv2.z * m2.z, mv2.w * m2.w);
        } else {
            float tpx = mv0.x * u0 + mv1.x * u1 + mv2.x * u2;
            float tpy = mv0.y * u0 + mv1.y * u1 + mv2.y * u2;
            float tpz = mv0.z * u0 + mv1.z * u1 + mv2.z * u2;
            float tpw = mv0.w * u0 + mv1.w * u1 + mv2.w * u2;
            os  = make_float4(tpx * m1.x, tpy * m1.y, tpz * m1.z, tpw * m1.w);
            ov0 = make_float4(ms.x * y0 * m2.x, ms.y * y0 * m2.y, ms.z * y0 * m2.z, ms.w * y0 * m2.w);
            ov1 = make_float4(ms.x * y1 * m2.x, ms.y * y1 * m2.y, ms.z * y1 * m2.z, ms.w * y1 * m2.w);
            ov2 = make_float4(ms.x * y2 * m2.x, ms.y * y2 * m2.y, ms.z * y2 * m2.z, ms.w * y2 * m2.w);
        }

        if (r != curr) {
            if (curr >= 0) {
                float* base = g_agg + (size_t)curr * 512;
                atomicAdd((float4*)(base + 4 * t),       aS);
                atomicAdd((float4*)(base + 128 + 4 * t), aV0);
                atomicAdd((float4*)(base + 256 + 4 * t), aV1);
                atomicAdd((float4*)(base + 384 + 4 * t), aV2);
            }
            curr = r;
            aS = os; aV0 = ov0; aV1 = ov1; aV2 = ov2;
        } else {
            aS.x += os.x;  aS.y += os.y;  aS.z += os.z;  aS.w += os.w;
            aV0.x += ov0.x; aV0.y += ov0.y; aV0.z += ov0.z; aV0.w += ov0.w;
            aV1.x += ov1.x; aV1.y += ov1.y; aV1.z += ov1.z; aV1.w += ov1.w;
            aV2.x += ov2.x; aV2.y += ov2.y; aV2.z += ov2.z; aV2.w += ov2.w;
        }
    }
    if (curr >= 0) {
        float* base = g_agg + (size_t)curr * 512;
        atomicAdd((float4*)(base + 4 * t),       aS);
        atomicAdd((float4*)(base + 128 + 4 * t), aV0);
        atomicAdd((float4*)(base + 256 + 4 * t), aV1);
        atomicAdd((float4*)(base + 384 + 4 * t), aV2);
    }
}

// =====================================================================
// Kernel 3 (R13): node "down" + skip + gate. 4 nodes/warp, vec weights.
// =====================================================================
__global__ void __launch_bounds__(128) k_node_down(
    const float* __restrict__ Wds, const float* __restrict__ Wdv,
    float* __restrict__ out)
{
    __shared__ __align__(16) float agi[4][512][4];
    int w = threadIdx.x >> 5, t = threadIdx.x & 31;
    int n0 = (blockIdx.x * 4 + w) * 4;

#pragma unroll
    for (int nl = 0; nl < 4; nl++) {
        const float4* src = (const float4*)(g_agg + (size_t)(n0 + nl) * 512);
#pragma unroll
        for (int q = 0; q < 4; q++) {
            float4 v = src[t + 32 * q];
            int i = 4 * t + 128 * q;
            agi[w][i + 0][nl] = v.x;
            agi[w][i + 1][nl] = v.y;
            agi[w][i + 2][nl] = v.z;
            agi[w][i + 3][nl] = v.w;
        }
    }
    __syncwarp();

    const float SCALE = INV128F * INVNN;

    u64 accS[4][2] = {};
#pragma unroll 4
    for (int i = 0; i < 128; i++) {
        float4 w4 = *(const float4*)(Wds + i * 128 + 4 * t);
        const u64* xp = (const u64*)agi[w][i];
        u64 x0 = xp[0], x1 = xp[1];
        u64 wp;
        wp = pack2(w4.x, w4.x); ffma2(accS[0][0], wp, x0); ffma2(accS[0][1], wp, x1);
        wp = pack2(w4.y, w4.y); ffma2(accS[1][0], wp, x0); ffma2(accS[1][1], wp, x1);
        wp = pack2(w4.z, w4.z); ffma2(accS[2][0], wp, x0); ffma2(accS[2][1], wp, x1);
        wp = pack2(w4.w, w4.w); ffma2(accS[3][0], wp, x0); ffma2(accS[3][1], wp, x1);
    }

    u64 accV[2][3][2] = {};
#pragma unroll 4
    for (int i = 0; i < 128; i++) {
        float2 w2 = *(const float2*)(Wdv + i * 64 + 2 * t);
        u64 wp0 = pack2(w2.x, w2.x), wp1 = pack2(w2.y, w2.y);
#pragma unroll
        for (int c = 0; c < 3; c++) {
            const u64* xp = (const u64*)agi[w][128 + 128 * c + i];
            u64 x0 = xp[0], x1 = xp[1];
            ffma2(accV[0][c][0], wp0, x0); ffma2(accV[0][c][1], wp0, x1);
            ffma2(accV[1][c][0], wp1, x0); ffma2(accV[1][c][1], wp1, x1);
        }
    }

#pragma unroll
    for (int nl = 0; nl < 4; nl++) {
        int n = n0 + nl;
        int p = nl >> 1, hi = nl & 1;
        const float* sc = g_sc + (size_t)n * 320;
        float4 sc4 = *(const float4*)(sc + 4 * t);
        float ds0, ds1, ds2, ds3;
        {
            float2 v0 = unpack2(accS[0][p]); ds0 = (hi ? v0.y : v0.x) * SCALE + sc4.x;
            float2 v1 = unpack2(accS[1][p]); ds1 = (hi ? v1.y : v1.x) * SCALE + sc4.y;
            float2 v2 = unpack2(accS[2][p]); ds2 = (hi ? v2.y : v2.x) * SCALE + sc4.z;
            float2 v3 = unpack2(accS[3][p]); ds3 = (hi ? v3.y : v3.x) * SCALE + sc4.w;
        }
        float sg0 = swishf(ds0), sg1 = swishf(ds1);
        float sg2 = swishf(ds2), sg3 = swishf(ds3);

        float* o = out + (size_t)n * 256;
        if (t < 16)
            *(float4*)(o + 4 * t) = make_float4(sg0, sg1, sg2, sg3);

        int src = 16 + (t >> 1);
        float gA = __shfl_sync(0xffffffffu, sg0, src);
        float gB = __shfl_sync(0xffffffffu, sg1, src);
        float gC = __shfl_sync(0xffffffffu, sg2, src);
        float gD = __shfl_sync(0xffffffffu, sg3, src);
        float g0 = (t & 1) ? gC : gA;
        float g1 = (t & 1) ? gD : gB;

        const float* scv = sc + 128 + 6 * t;
        float ev[6];
#pragma unroll
        for (int c = 0; c < 3; c++) {
            float2 v0 = unpack2(accV[0][c][p]);
            float2 v1 = unpack2(accV[1][c][p]);
            ev[c]     = ((hi ? v0.y : v0.x) * SCALE + scv[c])     * g0;
            ev[3 + c] = ((hi ? v1.y : v1.x) * SCALE + scv[3 + c]) * g1;
        }
        float* ov = o + 64 + 6 * t;
        *(float2*)(ov + 0) = make_float2(ev[0], ev[1]);
        *(float2*)(ov + 2) = make_float2(ev[2], ev[3]);
        *(float2*)(ov + 4) = make_float2(ev[4], ev[5]);
    }
}

// =====================================================================
extern "C" void kernel_launch(void* const* d_in, const int* in_sizes, int n_in,
                              void* d_out, int out_size)
{
    const float* vectors      = (const float*)d_in[0];
    const float* node_scalars = (const float*)d_in[1];
    const float* node_vectors = (const float*)d_in[2];
    const int*   node_specie  = (const int*)  d_in[3];
    const int*   senders      = (const int*)  d_in[4];
    const int*   receivers    = (const int*)  d_in[5];
    const float* W_up_s       = (const float*)d_in[6];
    const float* W_up_v       = (const float*)d_in[7];
    const float* W_skip_s     = (const float*)d_in[8];
    const float* W_skip_v     = (const float*)d_in[9];
    const float* W_mlp1       = (const float*)d_in[10];
    const float* W_mlp2       = (const float*)d_in[11];
    const float* W_mlp3       = (const float*)d_in[12];
    const float* W_down_s     = (const float*)d_in[13];
    const float* W_down_v     = (const float*)d_in[14];
    float* out = (float*)d_out;

    // Lazily-created side streams/events (first call is uncaptured, so
    // creation never happens during graph capture; reused thereafter).
    static cudaStream_t sA = nullptr, sB = nullptr;
    static cudaEvent_t evFork = nullptr, evA = nullptr, evB = nullptr;
    if (!sA) {
        cudaStreamCreateWithFlags(&sA, cudaStreamNonBlocking);
        cudaStreamCreateWithFlags(&sB, cudaStreamNonBlocking);
        cudaEventCreateWithFlags(&evFork, cudaEventDisableTiming);
        cudaEventCreateWithFlags(&evA, cudaEventDisableTiming);
        cudaEventCreateWithFlags(&evB, cudaEventDisableTiming);
    }

    void* aggp = nullptr; cudaGetSymbolAddress(&aggp, g_agg);
    void* cntp = nullptr; cudaGetSymbolAddress(&cntp, g_cnt);

    cudaEventRecord(evFork, 0);
    cudaStreamWaitEvent(sA, evFork, 0);
    cudaStreamWaitEvent(sB, evFork, 0);

    // Branch A: agg zero + node_up
    cudaMemsetAsync(aggp, 0, (size_t)N_NODES * 512 * sizeof(float), sA);
    k_node_up<<<N_NODES / 16, 256, 0, sA>>>(node_scalars, node_vectors, node_specie,
                                            W_up_s, W_up_v, W_skip_s, W_skip_v);
    cudaEventRecord(evA, sA);

    // Branch B: edge sort + payload + radial table
    cudaMemsetAsync(cntp, 0, N_NODES * sizeof(int), sB);
    k_hist<<<(N_EDGES + 255) / 256, 256, 0, sB>>>(receivers);
    k_scan<<<1, SCAN_T, 0, sB>>>();
    k_scatter<<<(N_EDGES + 255) / 256, 256, 0, sB>>>(receivers, senders, vectors);
    cudaFuncSetAttribute(k_table, cudaFuncAttributeMaxDynamicSharedMemorySize, 20480 * 4);
    k_table<<<TBL / 16, 256, 20480 * 4, sB>>>(W_mlp1, W_mlp2, W_mlp3);
    cudaEventRecord(evB, sB);

    // Join on the main stream, then edge + node_down
    cudaStreamWaitEvent(0, evA, 0);
    cudaStreamWaitEvent(0, evB, 0);

    k_edge<<<N_EDGES / (K2W * EPW), 256>>>();
    k_node_down<<<N_NODES / 16, 128>>>(W_down_s, W_down_v, out);
}